// round 8
// baseline (speedup 1.0000x reference)
#include <cuda_runtime.h>
#include <math.h>

#define NN      50000
#define NE      800000
#define F0      64
#define F1      128
#define F2      32
#define TPB     1024
#define NCHUNK  49              // ceil(NN / 1024)
#define NTILES  ((NN + 31) / 32)
#define SMEM_BYTES 163840       // max over phases (gemm2: 16KB W + 8*18KB A)

// ---------------- persistent scratch ----------------------------------------
__device__ float g_ax[NN * F0];
__device__ float g_a1[NN * F1];
__device__ float g_h2[NN * F2];
__device__ float g_dinv[NN];
__device__ int   g_cnt[NN];      // zero at load; self-zeroed each run in P1
__device__ int   g_fill[NN];
__device__ int   g_rowptr[NN + 1];
__device__ int   g_blksum[64];
__device__ int   g_colsrc[NE];
__device__ unsigned          g_arrive;    // barrier arrival counter
__device__ volatile unsigned g_release;   // barrier release generation (monotonic)

// ---------------- packed f32x2 helpers --------------------------------------
__device__ __forceinline__ void ffma2(unsigned long long& d,
                                      unsigned long long a,
                                      unsigned long long b) {
    asm("fma.rn.f32x2 %0, %1, %2, %0;" : "+l"(d) : "l"(a), "l"(b));
}
__device__ __forceinline__ unsigned long long pack2(float x, float y) {
    unsigned long long r;
    asm("mov.b64 %0, {%1, %2};" : "=l"(r) : "f"(x), "f"(y));
    return r;
}
__device__ __forceinline__ void unpack2(unsigned long long v, float& x, float& y) {
    asm("mov.b64 {%0, %1}, %2;" : "=f"(x), "=f"(y) : "l"(v));
}

// ---------------- grid-wide barrier (all blocks co-resident) -----------------
__device__ __forceinline__ void gridbar() {
    __syncthreads();
    if (threadIdx.x == 0) {
        unsigned target = g_release + 1;    // volatile read; constant between releases
        __threadfence();
        unsigned t = atomicAdd(&g_arrive, 1u);
        if (t == gridDim.x - 1) {
            atomicExch(&g_arrive, 0u);
            __threadfence();
            g_release = target;
        } else {
            while ((int)(g_release - target) < 0) __nanosleep(64);
        }
        __threadfence();
    }
    __syncthreads();
}

// ---------------- the whole GCN in one persistent kernel ---------------------
__global__ void __launch_bounds__(TPB) k_mega(
    const float* __restrict__ x,  const int* __restrict__ src,
    const int* __restrict__ dst,
    const float* __restrict__ W1, const float* __restrict__ b1,
    const float* __restrict__ W2, const float* __restrict__ b2,
    const float* __restrict__ Wc, const float* __restrict__ bc,
    float* __restrict__ out, float* __restrict__ hout)
{
    extern __shared__ unsigned char smem_raw[];
    const int tid = threadIdx.x;
    const int b   = blockIdx.x;
    const int NB  = gridDim.x;
    const int gstride = NB * TPB;

    // ---- P0: degree count -------------------------------------------------
    for (int e = b * TPB + tid; e < NE; e += gstride)
        atomicAdd(&g_cnt[dst[e]], 1);
    gridbar();

    // ---- P1: per-chunk exclusive scan (+dinv, +cnt reset) -----------------
    {
        int* s = (int*)smem_raw;
        if (b < NCHUNK) {
            int i = b * TPB + tid;
            int v = 0;
            if (i < NN) {
                v = g_cnt[i];
                g_cnt[i] = 0;                           // ready for next replay
                g_dinv[i] = rsqrtf((float)(v + 1));     // +1 self loop
            }
            s[tid] = v;
            __syncthreads();
            #pragma unroll
            for (int off = 1; off < TPB; off <<= 1) {
                int t2 = (tid >= off) ? s[tid - off] : 0;
                __syncthreads();
                s[tid] += t2;
                __syncthreads();
            }
            if (i < NN) g_rowptr[i] = s[tid] - v;
            if (tid == TPB - 1) g_blksum[b] = s[tid];
        }
    }
    gridbar();

    // ---- P2: redundant scan of chunk sums + finalize rowptr/fill ----------
    {
        int* s = (int*)smem_raw;
        if (tid < 64) s[tid] = (tid < NCHUNK) ? g_blksum[tid] : 0;
        __syncthreads();
        #pragma unroll
        for (int off = 1; off < 64; off <<= 1) {
            int u = (tid < 64 && tid >= off) ? s[tid - off] : 0;
            __syncthreads();
            if (tid < 64) s[tid] += u;
            __syncthreads();
        }
        for (int i = b * TPB + tid; i < NN; i += gstride) {
            int blk = i >> 10;
            int add = blk ? s[blk - 1] : 0;
            int r = g_rowptr[i] + add;
            g_rowptr[i] = r;
            g_fill[i] = r;
        }
        if (b == 0 && tid == 0) g_rowptr[NN] = NE;
    }
    gridbar();

    // ---- P3: scatter src ids into CSR -------------------------------------
    for (int e = b * TPB + tid; e < NE; e += gstride) {
        int pos = atomicAdd(&g_fill[dst[e]], 1);
        g_colsrc[pos] = src[e];
    }
    gridbar();

    // ---- P4: aggregate x (warp per node, float2/lane, unroll 8) -----------
    {
        const int lane = tid & 31;
        const int nwarps = NB * (TPB / 32);
        const float2* X = (const float2*)x;
        for (int n = b * (TPB / 32) + (tid >> 5); n < NN; n += nwarps) {
            float dn = g_dinv[n];
            float2 sv = X[n * 32 + lane];
            float ax = dn * sv.x, ay = dn * sv.y;
            int e = g_rowptr[n], end = g_rowptr[n + 1];
            for (; e + 7 < end; e += 8) {
                int si[8];
                #pragma unroll
                for (int u = 0; u < 8; u++) si[u] = g_colsrc[e + u];
                float dv[8];
                #pragma unroll
                for (int u = 0; u < 8; u++) dv[u] = g_dinv[si[u]];
                float2 vv[8];
                #pragma unroll
                for (int u = 0; u < 8; u++) vv[u] = X[si[u] * 32 + lane];
                #pragma unroll
                for (int u = 0; u < 8; u++) {
                    ax = fmaf(dv[u], vv[u].x, ax);
                    ay = fmaf(dv[u], vv[u].y, ay);
                }
            }
            for (; e < end; e++) {
                int sc = g_colsrc[e];
                float d = g_dinv[sc];
                float2 v = X[sc * 32 + lane];
                ax = fmaf(d, v.x, ax);
                ay = fmaf(d, v.y, ay);
            }
            float2 o; o.x = dn * ax; o.y = dn * ay;
            ((float2*)g_ax)[n * 32 + lane] = o;
        }
    }
    gridbar();

    // ---- P5: gemm1 a1 = relu(ax @ W1 + b1), 8 groups x 128 threads --------
    {
        float* sW = (float*)smem_raw;                       // 32 KB
        {
            const float4* Wp = (const float4*)W1;
            float4* Sp = (float4*)sW;
            for (int i = tid; i < F0 * F1 / 4; i += TPB) Sp[i] = Wp[i];
        }
        __syncthreads();
        const int gid = tid >> 7, ltid = tid & 127;
        float* sA = (float*)(smem_raw + 32768 + gid * 9216); // 64*36*4 each
        const int cg = ltid & 15, jg = ltid >> 4;
        const int c0 = cg * 8, j0 = jg * 4;
        float bl[8];
        #pragma unroll
        for (int i = 0; i < 8; i++) bl[i] = __ldg(&b1[c0 + i]);

        for (int t5 = b * 8 + gid; t5 < NTILES; t5 += NB * 8) {
            int n0 = t5 * 32;
            for (int idx = ltid; idx < 32 * F0; idx += 128) {
                int j = idx >> 6, k = idx & 63;
                sA[k * 36 + j] = (n0 + j < NN) ? g_ax[(n0 + j) * F0 + k] : 0.f;
            }
            asm volatile("bar.sync %0, 128;" :: "r"(1 + gid) : "memory");

            unsigned long long acc[4][4];
            #pragma unroll
            for (int a = 0; a < 4; a++)
                #pragma unroll
                for (int c = 0; c < 4; c++) acc[a][c] = 0ULL;

            #pragma unroll 4
            for (int k = 0; k < F0; k++) {
                const ulonglong2* Wp2 = (const ulonglong2*)&sW[k * F1 + c0];
                ulonglong2 wA = Wp2[0], wB = Wp2[1];
                float4 av = *(const float4*)&sA[k * 36 + j0];
                unsigned long long a0 = pack2(av.x, av.x);
                unsigned long long a1 = pack2(av.y, av.y);
                unsigned long long a2 = pack2(av.z, av.z);
                unsigned long long a3 = pack2(av.w, av.w);
                ffma2(acc[0][0], a0, wA.x); ffma2(acc[0][1], a0, wA.y);
                ffma2(acc[0][2], a0, wB.x); ffma2(acc[0][3], a0, wB.y);
                ffma2(acc[1][0], a1, wA.x); ffma2(acc[1][1], a1, wA.y);
                ffma2(acc[1][2], a1, wB.x); ffma2(acc[1][3], a1, wB.y);
                ffma2(acc[2][0], a2, wA.x); ffma2(acc[2][1], a2, wA.y);
                ffma2(acc[2][2], a2, wB.x); ffma2(acc[2][3], a2, wB.y);
                ffma2(acc[3][0], a3, wA.x); ffma2(acc[3][1], a3, wA.y);
                ffma2(acc[3][2], a3, wB.x); ffma2(acc[3][3], a3, wB.y);
            }

            #pragma unroll
            for (int jj = 0; jj < 4; jj++) {
                int n = n0 + j0 + jj;
                if (n < NN) {
                    float* o = &g_a1[n * F1 + c0];
                    #pragma unroll
                    for (int p = 0; p < 4; p++) {
                        float lo, hi;
                        unpack2(acc[jj][p], lo, hi);
                        o[2 * p]     = fmaxf(lo + bl[2 * p], 0.f);
                        o[2 * p + 1] = fmaxf(hi + bl[2 * p + 1], 0.f);
                    }
                }
            }
            asm volatile("bar.sync %0, 128;" :: "r"(1 + gid) : "memory");
        }
    }
    gridbar();

    // ---- P6: gemm2 h2 = a1 @ W2, 8 groups x 128 threads -------------------
    {
        float* sW = (float*)smem_raw;                       // 16 KB
        {
            const float4* Wp = (const float4*)W2;
            float4* Sp = (float4*)sW;
            for (int i = tid; i < F1 * F2 / 4; i += TPB) Sp[i] = Wp[i];
        }
        __syncthreads();
        const int gid = tid >> 7, ltid = tid & 127;
        float* sA = (float*)(smem_raw + 16384 + gid * 18432); // 128*36*4 each
        const int cg = ltid & 15, jg = ltid >> 4;
        const int c0 = cg * 2, j0 = jg * 4;

        for (int t6 = b * 8 + gid; t6 < NTILES; t6 += NB * 8) {
            int n0 = t6 * 32;
            for (int idx = ltid; idx < 32 * F1; idx += 128) {
                int j = idx >> 7, k = idx & 127;
                sA[k * 36 + j] = (n0 + j < NN) ? g_a1[(n0 + j) * F1 + k] : 0.f;
            }
            asm volatile("bar.sync %0, 128;" :: "r"(1 + gid) : "memory");

            unsigned long long acc[4];
            #pragma unroll
            for (int a = 0; a < 4; a++) acc[a] = 0ULL;

            #pragma unroll 8
            for (int k = 0; k < F1; k++) {
                unsigned long long w = *(const unsigned long long*)&sW[k * F2 + c0];
                float4 av = *(const float4*)&sA[k * 36 + j0];
                ffma2(acc[0], pack2(av.x, av.x), w);
                ffma2(acc[1], pack2(av.y, av.y), w);
                ffma2(acc[2], pack2(av.z, av.z), w);
                ffma2(acc[3], pack2(av.w, av.w), w);
            }

            #pragma unroll
            for (int jj = 0; jj < 4; jj++) {
                int n = n0 + j0 + jj;
                if (n < NN)
                    ((unsigned long long*)g_h2)[n * 16 + cg] = acc[jj];
            }
            asm volatile("bar.sync %0, 128;" :: "r"(1 + gid) : "memory");
        }
    }
    gridbar();

    // ---- P7: fused agg2 + classifier --------------------------------------
    {
        float* sWc = (float*)smem_raw;                      // 4 KB
        for (int i = tid; i < F2 * F2; i += TPB) sWc[i] = Wc[i];
        __syncthreads();

        const int lane = tid & 31;
        const int nwarps = NB * (TPB / 32);
        const float b2l = b2[lane];
        const float bcl = bc[lane];

        for (int n = b * (TPB / 32) + (tid >> 5); n < NN; n += nwarps) {
            float dn = g_dinv[n];
            float acc = dn * g_h2[n * F2 + lane];
            int e = g_rowptr[n], end = g_rowptr[n + 1];
            for (; e + 7 < end; e += 8) {
                int si[8];
                #pragma unroll
                for (int u = 0; u < 8; u++) si[u] = g_colsrc[e + u];
                float dv[8];
                #pragma unroll
                for (int u = 0; u < 8; u++) dv[u] = g_dinv[si[u]];
                float hv[8];
                #pragma unroll
                for (int u = 0; u < 8; u++) hv[u] = g_h2[si[u] * F2 + lane];
                #pragma unroll
                for (int u = 0; u < 8; u++) acc = fmaf(dv[u], hv[u], acc);
            }
            for (; e < end; e++) {
                int s = g_colsrc[e];
                acc = fmaf(g_dinv[s], g_h2[s * F2 + lane], acc);
            }

            float h = dn * acc + b2l;
            hout[n * F2 + lane] = h;

            float o = 0.f;
            #pragma unroll
            for (int k = 0; k < F2; k++) {
                float hk = __shfl_sync(0xFFFFFFFFu, h, k);
                o = fmaf(hk, sWc[k * F2 + lane], o);
            }
            out[n * F2 + lane] = o + bcl;
        }
    }
}

// ---------------- launch -----------------------------------------------------
extern "C" void kernel_launch(void* const* d_in, const int* in_sizes, int n_in,
                              void* d_out, int out_size) {
    const float* x   = (const float*)d_in[0];
    const int*   ei  = (const int*)d_in[1];
    const float* W1  = (const float*)d_in[2];
    const float* b1  = (const float*)d_in[3];
    const float* W2  = (const float*)d_in[4];
    const float* b2  = (const float*)d_in[5];
    const float* Wc  = (const float*)d_in[6];
    const float* bc  = (const float*)d_in[7];

    const int* src = ei;
    const int* dst = ei + NE;

    float* out  = (float*)d_out;            // [NN, F2]
    float* hout = (float*)d_out + NN * F2;  // [NN, F2]

    cudaFuncSetAttribute(k_mega, cudaFuncAttributeMaxDynamicSharedMemorySize,
                         SMEM_BYTES);

    int nsm = 0;
    cudaDeviceGetAttribute(&nsm, cudaDevAttrMultiProcessorCount, 0);
    if (nsm <= 0) nsm = 148;

    // 1024 threads, <=64 regs, 160KB smem -> exactly 1 block/SM, all co-resident
    k_mega<<<nsm, TPB, SMEM_BYTES>>>(x, src, dst, W1, b1, W2, b2, Wc, bc,
                                     out, hout);
}

// round 9
// speedup vs baseline: 1.2557x; 1.2557x over previous
#include <cuda_runtime.h>
#include <math.h>

#define NN      50000
#define NE      800000
#define F0      64
#define F1      128
#define F2      32
#define SCAN_B  1024
#define NBLK    ((NN + SCAN_B - 1) / SCAN_B)   // 49

// ---------------- scratch (static device globals) ----------------------------
__device__ float g_ax[NN * F0];     // aggregated x
__device__ float g_h2[NN * F2];     // a1 @ W2
__device__ float g_dinv[NN];
__device__ int   g_cnt[NN];         // zero at load; self-zeroed by k_scan1 each run
__device__ int   g_fill[NN];        // chunk-local partial offsets (scatter cursor)
__device__ int   g_rowptr[NN + 1];  // chunk-local partial rowptr
__device__ int   g_blksum[64];      // per-chunk totals
__device__ int   g_colsrc[NE];

// ---------------- packed f32x2 helpers --------------------------------------
__device__ __forceinline__ void ffma2(unsigned long long& d,
                                      unsigned long long a,
                                      unsigned long long b) {
    asm("fma.rn.f32x2 %0, %1, %2, %0;" : "+l"(d) : "l"(a), "l"(b));
}
__device__ __forceinline__ unsigned long long pack2(float x, float y) {
    unsigned long long r;
    asm("mov.b64 %0, {%1, %2};" : "=l"(r) : "f"(x), "f"(y));
    return r;
}
__device__ __forceinline__ void unpack2(unsigned long long v, float& x, float& y) {
    asm("mov.b64 {%0, %1}, %2;" : "=f"(x), "=f"(y) : "l"(v));
}

// Load 49 chunk sums into smem and turn them into an INCLUSIVE prefix.
// All threads of the block must participate (guarded __syncthreads pattern).
__device__ __forceinline__ void chunk_prefix(int* sPre) {
    int t = threadIdx.x;
    if (t < 64) sPre[t] = (t < NBLK) ? g_blksum[t] : 0;
    __syncthreads();
    #pragma unroll
    for (int off = 1; off < 64; off <<= 1) {
        int u = (t < 64 && t >= off) ? sPre[t - off] : 0;
        __syncthreads();
        if (t < 64) sPre[t] += u;
        __syncthreads();
    }
}
__device__ __forceinline__ int pre_of(const int* sPre, int i) {
    int blk = i >> 10;
    return blk ? sPre[blk - 1] : 0;
}

// ---------------- CSR build --------------------------------------------------
__global__ void k_count(const int* __restrict__ dst) {
    int e = blockIdx.x * blockDim.x + threadIdx.x;
    if (e < NE) atomicAdd(&g_cnt[dst[e]], 1);
}

// per-chunk scan: rowptr/fill get chunk-LOCAL exclusive offsets; blksum gets totals
__global__ void k_scan1() {
    __shared__ int s[SCAN_B];
    int tid = threadIdx.x;
    int i = blockIdx.x * SCAN_B + tid;
    int v = 0;
    if (i < NN) {
        v = g_cnt[i];
        g_cnt[i] = 0;                                 // reset for next replay
        g_dinv[i] = rsqrtf((float)(v + 1));           // +1 self loop
    }
    s[tid] = v;
    __syncthreads();
    #pragma unroll
    for (int off = 1; off < SCAN_B; off <<= 1) {
        int t = (tid >= off) ? s[tid - off] : 0;
        __syncthreads();
        s[tid] += t;
        __syncthreads();
    }
    if (i < NN) {
        int excl = s[tid] - v;
        g_rowptr[i] = excl;
        g_fill[i] = excl;
        if (i == NN - 1) g_rowptr[NN] = s[tid];       // inclusive partial of last chunk
    }
    if (tid == SCAN_B - 1) g_blksum[blockIdx.x] = s[tid];
}

__global__ void __launch_bounds__(256) k_scatter(const int* __restrict__ src,
                                                 const int* __restrict__ dst) {
    __shared__ int sPre[64];
    chunk_prefix(sPre);
    int e = blockIdx.x * 256 + threadIdx.x;
    if (e < NE) {
        int d = dst[e];
        int pos = atomicAdd(&g_fill[d], 1) + pre_of(sPre, d);
        g_colsrc[pos] = src[e];
    }
}

// ---------------- Aggregate x (F=64, warp per node, float2, unroll 8) --------
__global__ void __launch_bounds__(256) k_aggx(const float* __restrict__ x) {
    __shared__ int sPre[64];
    chunk_prefix(sPre);

    int gtid = blockIdx.x * 256 + threadIdx.x;
    int n = gtid >> 5;
    int lane = gtid & 31;
    if (n >= NN) return;

    const float2* X = (const float2*)x;     // row = 32 float2
    float dn = g_dinv[n];
    float2 s = X[n * 32 + lane];
    float ax = dn * s.x, ay = dn * s.y;

    int e   = g_rowptr[n]     + pre_of(sPre, n);
    int end = g_rowptr[n + 1] + pre_of(sPre, n + 1);
    for (; e + 7 < end; e += 8) {
        int si[8];
        #pragma unroll
        for (int u = 0; u < 8; u++) si[u] = g_colsrc[e + u];
        float dv[8];
        #pragma unroll
        for (int u = 0; u < 8; u++) dv[u] = g_dinv[si[u]];
        float2 vv[8];
        #pragma unroll
        for (int u = 0; u < 8; u++) vv[u] = X[si[u] * 32 + lane];
        #pragma unroll
        for (int u = 0; u < 8; u++) {
            ax = fmaf(dv[u], vv[u].x, ax);
            ay = fmaf(dv[u], vv[u].y, ay);
        }
    }
    for (; e < end; e++) {
        int sc = g_colsrc[e];
        float d = g_dinv[sc];
        float2 v = X[sc * 32 + lane];
        ax = fmaf(d, v.x, ax);
        ay = fmaf(d, v.y, ay);
    }
    float2 o; o.x = dn * ax; o.y = dn * ay;
    ((float2*)g_ax)[n * 32 + lane] = o;
}

// ---- Fused GEMM1+GEMM2: h2 = relu(ax@W1 + b1) @ W2, a1 stays in smem -------
// dynamic smem layout (floats):
//   sW1 [0, 8192)        64x128
//   sA  [8192, 10496)    64x36   (ax tile, k-major, padded)
//   sW2 [10496, 14592)   128x32
//   sB  [14592, 19200)   128x36  (a1 tile, k-major, padded)
#define G12_SMEM_FLOATS 19200
__global__ void __launch_bounds__(128) k_gemm12(const float* __restrict__ W1,
                                                const float* __restrict__ b1,
                                                const float* __restrict__ W2) {
    extern __shared__ float sm[];
    float* sW1 = sm;
    float* sA  = sm + 8192;
    float* sW2 = sm + 10496;
    float* sB  = sm + 14592;

    int tid = threadIdx.x;
    int n0 = blockIdx.x * 32;

    // stage weights
    {
        const float4* Wp = (const float4*)W1;
        float4* Sp = (float4*)sW1;
        #pragma unroll
        for (int i = tid; i < F0 * F1 / 4; i += 128) Sp[i] = Wp[i];
        const float4* W2p = (const float4*)W2;
        float4* S2p = (float4*)sW2;
        #pragma unroll
        for (int i = tid; i < F1 * F2 / 4; i += 128) S2p[i] = W2p[i];
    }
    // stage ax tile k-major
    for (int idx = tid; idx < 32 * F0; idx += 128) {
        int j = idx >> 6, k = idx & 63;
        sA[k * 36 + j] = (n0 + j < NN) ? g_ax[(n0 + j) * F0 + k] : 0.f;
    }
    __syncthreads();

    // ---- phase 1: a1 = relu(ax @ W1 + b1) -> sB (k-major) ----
    {
        int cg = tid & 15, jg = tid >> 4;   // 16 col-groups x 8 node-groups
        int c0 = cg * 8, j0 = jg * 4;

        unsigned long long acc[4][4];
        #pragma unroll
        for (int a = 0; a < 4; a++)
            #pragma unroll
            for (int c = 0; c < 4; c++) acc[a][c] = 0ULL;

        #pragma unroll 4
        for (int k = 0; k < F0; k++) {
            const ulonglong2* Wp = (const ulonglong2*)&sW1[k * F1 + c0];
            ulonglong2 wA = Wp[0], wB = Wp[1];
            float4 av = *(const float4*)&sA[k * 36 + j0];
            unsigned long long a0 = pack2(av.x, av.x);
            unsigned long long a1 = pack2(av.y, av.y);
            unsigned long long a2 = pack2(av.z, av.z);
            unsigned long long a3 = pack2(av.w, av.w);
            ffma2(acc[0][0], a0, wA.x); ffma2(acc[0][1], a0, wA.y);
            ffma2(acc[0][2], a0, wB.x); ffma2(acc[0][3], a0, wB.y);
            ffma2(acc[1][0], a1, wA.x); ffma2(acc[1][1], a1, wA.y);
            ffma2(acc[1][2], a1, wB.x); ffma2(acc[1][3], a1, wB.y);
            ffma2(acc[2][0], a2, wA.x); ffma2(acc[2][1], a2, wA.y);
            ffma2(acc[2][2], a2, wB.x); ffma2(acc[2][3], a2, wB.y);
            ffma2(acc[3][0], a3, wA.x); ffma2(acc[3][1], a3, wA.y);
            ffma2(acc[3][2], a3, wB.x); ffma2(acc[3][3], a3, wB.y);
        }

        float bl[8];
        #pragma unroll
        for (int i = 0; i < 8; i++) bl[i] = __ldg(&b1[c0 + i]);

        // write relu(acc+b) into sB[col*36 + node], float4 over the 4 nodes
        #pragma unroll
        for (int p = 0; p < 4; p++) {
            float lo0, hi0;
            float4 vlo, vhi;
            unpack2(acc[0][p], lo0, hi0); vlo.x = lo0; vhi.x = hi0;
            unpack2(acc[1][p], lo0, hi0); vlo.y = lo0; vhi.y = hi0;
            unpack2(acc[2][p], lo0, hi0); vlo.z = lo0; vhi.z = hi0;
            unpack2(acc[3][p], lo0, hi0); vlo.w = lo0; vhi.w = hi0;
            float blo = bl[2 * p], bhi = bl[2 * p + 1];
            vlo.x = fmaxf(vlo.x + blo, 0.f); vlo.y = fmaxf(vlo.y + blo, 0.f);
            vlo.z = fmaxf(vlo.z + blo, 0.f); vlo.w = fmaxf(vlo.w + blo, 0.f);
            vhi.x = fmaxf(vhi.x + bhi, 0.f); vhi.y = fmaxf(vhi.y + bhi, 0.f);
            vhi.z = fmaxf(vhi.z + bhi, 0.f); vhi.w = fmaxf(vhi.w + bhi, 0.f);
            *(float4*)&sB[(c0 + 2 * p) * 36 + j0]     = vlo;
            *(float4*)&sB[(c0 + 2 * p + 1) * 36 + j0] = vhi;
        }
    }
    __syncthreads();

    // ---- phase 2: h2 = a1 @ W2 ----
    {
        int cg = tid & 15, jg = tid >> 4;   // 16 col-groups (2 cols) x 8 node-groups (4)
        int c0 = cg * 2, j0 = jg * 4;

        unsigned long long acc[4];
        #pragma unroll
        for (int a = 0; a < 4; a++) acc[a] = 0ULL;

        #pragma unroll 8
        for (int k = 0; k < F1; k++) {
            unsigned long long w = *(const unsigned long long*)&sW2[k * F2 + c0];
            float4 av = *(const float4*)&sB[k * 36 + j0];
            ffma2(acc[0], pack2(av.x, av.x), w);
            ffma2(acc[1], pack2(av.y, av.y), w);
            ffma2(acc[2], pack2(av.z, av.z), w);
            ffma2(acc[3], pack2(av.w, av.w), w);
        }

        #pragma unroll
        for (int jj = 0; jj < 4; jj++) {
            int n = n0 + j0 + jj;
            if (n < NN)
                ((unsigned long long*)g_h2)[n * 16 + cg] = acc[jj];
        }
    }
}

// ------- Fused agg2 + classifier: h = agg(h2)+b2 ; out = h @ Wc + bc --------
__global__ void __launch_bounds__(256) k_agg2g3(const float* __restrict__ b2,
                                                const float* __restrict__ Wc,
                                                const float* __restrict__ bc,
                                                float* __restrict__ out,
                                                float* __restrict__ hout) {
    __shared__ int sPre[64];
    __shared__ float sW[F2 * F2];        // Wc, 4 KB, [k][c]
    int tid = threadIdx.x;
    for (int i = tid; i < F2 * F2; i += 256) sW[i] = Wc[i];
    chunk_prefix(sPre);                  // includes the needed __syncthreads

    int gtid = blockIdx.x * 256 + tid;
    int n = gtid >> 5;
    int lane = gtid & 31;
    if (n >= NN) return;

    float dn = g_dinv[n];
    float acc = dn * g_h2[n * F2 + lane];

    int e   = g_rowptr[n]     + pre_of(sPre, n);
    int end = g_rowptr[n + 1] + pre_of(sPre, n + 1);
    for (; e + 7 < end; e += 8) {
        int si[8];
        #pragma unroll
        for (int u = 0; u < 8; u++) si[u] = g_colsrc[e + u];
        float dv[8];
        #pragma unroll
        for (int u = 0; u < 8; u++) dv[u] = g_dinv[si[u]];
        float hv[8];
        #pragma unroll
        for (int u = 0; u < 8; u++) hv[u] = g_h2[si[u] * F2 + lane];
        #pragma unroll
        for (int u = 0; u < 8; u++) acc = fmaf(dv[u], hv[u], acc);
    }
    for (; e < end; e++) {
        int s = g_colsrc[e];
        acc = fmaf(g_dinv[s], g_h2[s * F2 + lane], acc);
    }

    float h = dn * acc + b2[lane];
    hout[n * F2 + lane] = h;

    float o = 0.f;
    #pragma unroll
    for (int k = 0; k < F2; k++) {
        float hk = __shfl_sync(0xFFFFFFFFu, h, k);
        o = fmaf(hk, sW[k * F2 + lane], o);
    }
    out[n * F2 + lane] = o + bc[lane];
}

// ---------------- launch -----------------------------------------------------
extern "C" void kernel_launch(void* const* d_in, const int* in_sizes, int n_in,
                              void* d_out, int out_size) {
    const float* x   = (const float*)d_in[0];
    const int*   ei  = (const int*)d_in[1];
    const float* W1  = (const float*)d_in[2];
    const float* b1  = (const float*)d_in[3];
    const float* W2  = (const float*)d_in[4];
    const float* b2  = (const float*)d_in[5];
    const float* Wc  = (const float*)d_in[6];
    const float* bc  = (const float*)d_in[7];

    const int* src = ei;
    const int* dst = ei + NE;

    float* out  = (float*)d_out;            // [NN, F2]
    float* hout = (float*)d_out + NN * F2;  // [NN, F2]

    static int smem_set = 0;
    if (!smem_set) {
        cudaFuncSetAttribute(k_gemm12, cudaFuncAttributeMaxDynamicSharedMemorySize,
                             G12_SMEM_FLOATS * 4);
        smem_set = 1;
    }

    int nb_edges = (NE + 255) / 256;
    int nb_gemm  = (NN + 31) / 32;

    // CSR build (g_cnt zero at entry; self-zeroed by k_scan1 each run)
    k_count<<<nb_edges, 256>>>(dst);
    k_scan1<<<NBLK, SCAN_B>>>();
    k_scatter<<<nb_edges, 256>>>(src, dst);

    // Layer 1+2: aggregate x, then fused gemm1->gemm2 (a1 never hits DRAM)
    k_aggx<<<(NN * 32 + 255) / 256, 256>>>(x);
    k_gemm12<<<nb_gemm, 128, G12_SMEM_FLOATS * 4>>>(W1, b1, W2);

    // agg2 + classifier fused
    k_agg2g3<<<(NN * 32 + 255) / 256, 256>>>(b2, Wc, bc, out, hout);
}

// round 10
// speedup vs baseline: 1.3260x; 1.0560x over previous
#include <cuda_runtime.h>
#include <cuda_fp16.h>
#include <math.h>

#define NN      50000
#define NE      800000
#define F0      64
#define F1      128
#define F2      32
#define SCAN_B  1024
#define NBLK    ((NN + SCAN_B - 1) / SCAN_B)   // 49

// ---------------- scratch (static device globals) ----------------------------
__device__ __half2 g_xs[NN * 32];   // dinv[n] * x[n], fp16, row = 32 half2 = 128B
__device__ float g_ax[NN * F0];     // aggregated x (fp32)
__device__ float g_h2s[NN * F2];    // dinv[n] * (a1 @ W2)
__device__ float g_dinv[NN];
__device__ int   g_cnt[NN];         // zero at load; self-zeroed by k_scan1 each run
__device__ int   g_fill[NN];
__device__ int   g_rowptr[NN + 1];
__device__ int   g_blksum[64];
__device__ int   g_colsrc[NE];

// ---------------- packed f32x2 helpers --------------------------------------
__device__ __forceinline__ void ffma2(unsigned long long& d,
                                      unsigned long long a,
                                      unsigned long long b) {
    asm("fma.rn.f32x2 %0, %1, %2, %0;" : "+l"(d) : "l"(a), "l"(b));
}
__device__ __forceinline__ unsigned long long pack2(float x, float y) {
    unsigned long long r;
    asm("mov.b64 %0, {%1, %2};" : "=l"(r) : "f"(x), "f"(y));
    return r;
}
__device__ __forceinline__ void unpack2(unsigned long long v, float& x, float& y) {
    asm("mov.b64 {%0, %1}, %2;" : "=f"(x), "=f"(y) : "l"(v));
}

// ---------------- CSR build --------------------------------------------------
__global__ void k_count(const int* __restrict__ dst) {
    int e = blockIdx.x * blockDim.x + threadIdx.x;
    if (e < NE) atomicAdd(&g_cnt[dst[e]], 1);
}

// per-chunk scan: chunk-local exclusive offsets; blksum gets chunk totals
__global__ void k_scan1() {
    __shared__ int s[SCAN_B];
    int tid = threadIdx.x;
    int i = blockIdx.x * SCAN_B + tid;
    int v = 0;
    if (i < NN) {
        v = g_cnt[i];
        g_cnt[i] = 0;                                 // reset for next replay
        g_dinv[i] = rsqrtf((float)(v + 1));           // +1 self loop
    }
    s[tid] = v;
    __syncthreads();
    #pragma unroll
    for (int off = 1; off < SCAN_B; off <<= 1) {
        int t = (tid >= off) ? s[tid - off] : 0;
        __syncthreads();
        s[tid] += t;
        __syncthreads();
    }
    if (i < NN) g_rowptr[i] = s[tid] - v;
    if (tid == SCAN_B - 1) g_blksum[blockIdx.x] = s[tid];
}

// finalize: add chunk prefix (re-scanned locally), init fill
__global__ void __launch_bounds__(256) k_scan3() {
    __shared__ int s[64];
    int t = threadIdx.x;
    if (t < 64) s[t] = (t < NBLK) ? g_blksum[t] : 0;
    __syncthreads();
    #pragma unroll
    for (int off = 1; off < 64; off <<= 1) {
        int u = (t < 64 && t >= off) ? s[t - off] : 0;
        __syncthreads();
        if (t < 64) s[t] += u;
        __syncthreads();
    }
    int i = blockIdx.x * 256 + t;
    if (i < NN) {
        int blk = i >> 10;
        int add = blk ? s[blk - 1] : 0;
        int r = g_rowptr[i] + add;
        g_rowptr[i] = r;
        g_fill[i] = r;
    }
    if (i == 0) g_rowptr[NN] = NE;
}

__global__ void k_scatter(const int* __restrict__ src, const int* __restrict__ dst) {
    int e = blockIdx.x * blockDim.x + threadIdx.x;
    if (e < NE) {
        int pos = atomicAdd(&g_fill[dst[e]], 1);
        g_colsrc[pos] = src[e];
    }
}

// ---------------- Prescale: xs = half2(dinv[n] * x[n]) ----------------------
__global__ void __launch_bounds__(256) k_prescale(const float* __restrict__ x) {
    int idx = blockIdx.x * 256 + threadIdx.x;     // over NN*32 half2 slots
    if (idx >= NN * 32) return;
    int n = idx >> 5;
    float d = g_dinv[n];
    float2 v = ((const float2*)x)[idx];
    g_xs[idx] = __floats2half2_rn(d * v.x, d * v.y);
}

// ---------------- Aggregate x: fp16 gathers, no dinv gather ------------------
// ax_n = dn * ( dn*x_n  +  sum_e xs[src_e] )
__global__ void __launch_bounds__(256) k_aggx(const float* __restrict__ x) {
    int gtid = blockIdx.x * blockDim.x + threadIdx.x;
    int n = gtid >> 5;
    int lane = gtid & 31;
    if (n >= NN) return;

    float dn = g_dinv[n];
    float2 sv = ((const float2*)x)[n * 32 + lane];
    float ax = dn * sv.x, ay = dn * sv.y;          // self term, fp32

    int e = g_rowptr[n], end = g_rowptr[n + 1];
    for (; e + 7 < end; e += 8) {
        int si[8];
        #pragma unroll
        for (int u = 0; u < 8; u++) si[u] = g_colsrc[e + u];
        __half2 hv[8];
        #pragma unroll
        for (int u = 0; u < 8; u++) hv[u] = g_xs[si[u] * 32 + lane];
        #pragma unroll
        for (int u = 0; u < 8; u++) {
            float2 f = __half22float2(hv[u]);
            ax += f.x; ay += f.y;
        }
    }
    for (; e < end; e++) {
        float2 f = __half22float2(g_xs[g_colsrc[e] * 32 + lane]);
        ax += f.x; ay += f.y;
    }
    float2 o; o.x = dn * ax; o.y = dn * ay;
    ((float2*)g_ax)[n * 32 + lane] = o;
}

// ---- Fused GEMM1+GEMM2: h2s = dinv * (relu(ax@W1 + b1) @ W2) ---------------
// dynamic smem (floats): sW1[0,8192) sA[8192,10496) sW2[10496,14592) sB[14592,19200)
#define G12_SMEM_FLOATS 19200
__global__ void __launch_bounds__(128) k_gemm12(const float* __restrict__ W1,
                                                const float* __restrict__ b1,
                                                const float* __restrict__ W2) {
    extern __shared__ float sm[];
    float* sW1 = sm;
    float* sA  = sm + 8192;
    float* sW2 = sm + 10496;
    float* sB  = sm + 14592;

    int tid = threadIdx.x;
    int n0 = blockIdx.x * 32;

    {
        const float4* Wp = (const float4*)W1;
        float4* Sp = (float4*)sW1;
        #pragma unroll
        for (int i = tid; i < F0 * F1 / 4; i += 128) Sp[i] = Wp[i];
        const float4* W2p = (const float4*)W2;
        float4* S2p = (float4*)sW2;
        #pragma unroll
        for (int i = tid; i < F1 * F2 / 4; i += 128) S2p[i] = W2p[i];
    }
    for (int idx = tid; idx < 32 * F0; idx += 128) {
        int j = idx >> 6, k = idx & 63;
        sA[k * 36 + j] = (n0 + j < NN) ? g_ax[(n0 + j) * F0 + k] : 0.f;
    }
    __syncthreads();

    // phase 1: a1 = relu(ax @ W1 + b1) -> sB (k-major)
    {
        int cg = tid & 15, jg = tid >> 4;
        int c0 = cg * 8, j0 = jg * 4;

        unsigned long long acc[4][4];
        #pragma unroll
        for (int a = 0; a < 4; a++)
            #pragma unroll
            for (int c = 0; c < 4; c++) acc[a][c] = 0ULL;

        #pragma unroll 4
        for (int k = 0; k < F0; k++) {
            const ulonglong2* Wp = (const ulonglong2*)&sW1[k * F1 + c0];
            ulonglong2 wA = Wp[0], wB = Wp[1];
            float4 av = *(const float4*)&sA[k * 36 + j0];
            unsigned long long a0 = pack2(av.x, av.x);
            unsigned long long a1 = pack2(av.y, av.y);
            unsigned long long a2 = pack2(av.z, av.z);
            unsigned long long a3 = pack2(av.w, av.w);
            ffma2(acc[0][0], a0, wA.x); ffma2(acc[0][1], a0, wA.y);
            ffma2(acc[0][2], a0, wB.x); ffma2(acc[0][3], a0, wB.y);
            ffma2(acc[1][0], a1, wA.x); ffma2(acc[1][1], a1, wA.y);
            ffma2(acc[1][2], a1, wB.x); ffma2(acc[1][3], a1, wB.y);
            ffma2(acc[2][0], a2, wA.x); ffma2(acc[2][1], a2, wA.y);
            ffma2(acc[2][2], a2, wB.x); ffma2(acc[2][3], a2, wB.y);
            ffma2(acc[3][0], a3, wA.x); ffma2(acc[3][1], a3, wA.y);
            ffma2(acc[3][2], a3, wB.x); ffma2(acc[3][3], a3, wB.y);
        }

        float bl[8];
        #pragma unroll
        for (int i = 0; i < 8; i++) bl[i] = __ldg(&b1[c0 + i]);

        #pragma unroll
        for (int p = 0; p < 4; p++) {
            float lo0, hi0;
            float4 vlo, vhi;
            unpack2(acc[0][p], lo0, hi0); vlo.x = lo0; vhi.x = hi0;
            unpack2(acc[1][p], lo0, hi0); vlo.y = lo0; vhi.y = hi0;
            unpack2(acc[2][p], lo0, hi0); vlo.z = lo0; vhi.z = hi0;
            unpack2(acc[3][p], lo0, hi0); vlo.w = lo0; vhi.w = hi0;
            float blo = bl[2 * p], bhi = bl[2 * p + 1];
            vlo.x = fmaxf(vlo.x + blo, 0.f); vlo.y = fmaxf(vlo.y + blo, 0.f);
            vlo.z = fmaxf(vlo.z + blo, 0.f); vlo.w = fmaxf(vlo.w + blo, 0.f);
            vhi.x = fmaxf(vhi.x + bhi, 0.f); vhi.y = fmaxf(vhi.y + bhi, 0.f);
            vhi.z = fmaxf(vhi.z + bhi, 0.f); vhi.w = fmaxf(vhi.w + bhi, 0.f);
            *(float4*)&sB[(c0 + 2 * p) * 36 + j0]     = vlo;
            *(float4*)&sB[(c0 + 2 * p + 1) * 36 + j0] = vhi;
        }
    }
    __syncthreads();

    // phase 2: h2s = dinv[n] * (a1 @ W2)
    {
        int cg = tid & 15, jg = tid >> 4;
        int c0 = cg * 2, j0 = jg * 4;

        unsigned long long acc[4];
        #pragma unroll
        for (int a = 0; a < 4; a++) acc[a] = 0ULL;

        #pragma unroll 8
        for (int k = 0; k < F1; k++) {
            unsigned long long w = *(const unsigned long long*)&sW2[k * F2 + c0];
            float4 av = *(const float4*)&sB[k * 36 + j0];
            ffma2(acc[0], pack2(av.x, av.x), w);
            ffma2(acc[1], pack2(av.y, av.y), w);
            ffma2(acc[2], pack2(av.z, av.z), w);
            ffma2(acc[3], pack2(av.w, av.w), w);
        }

        #pragma unroll
        for (int jj = 0; jj < 4; jj++) {
            int n = n0 + j0 + jj;
            if (n < NN) {
                float dnn = g_dinv[n];
                float lo, hi;
                unpack2(acc[jj], lo, hi);
                float2 r; r.x = dnn * lo; r.y = dnn * hi;
                *(float2*)&g_h2s[n * F2 + c0] = r;
            }
        }
    }
}

// ------- Fused agg2 + classifier: no dinv gather ----------------------------
// h_n = dn * ( h2s[n] + sum_e h2s[src_e] ) + b2 ; out = h @ Wc + bc
__global__ void __launch_bounds__(256) k_agg2g3(const float* __restrict__ b2,
                                                const float* __restrict__ Wc,
                                                const float* __restrict__ bc,
                                                float* __restrict__ out,
                                                float* __restrict__ hout) {
    __shared__ float sW[F2 * F2];
    int tid = threadIdx.x;
    for (int i = tid; i < F2 * F2; i += 256) sW[i] = Wc[i];
    __syncthreads();

    int gtid = blockIdx.x * 256 + tid;
    int n = gtid >> 5;
    int lane = gtid & 31;
    if (n >= NN) return;

    float dn = g_dinv[n];
    float acc = g_h2s[n * F2 + lane];              // self term (already dinv-scaled)

    int e = g_rowptr[n], end = g_rowptr[n + 1];
    for (; e + 7 < end; e += 8) {
        int si[8];
        #pragma unroll
        for (int u = 0; u < 8; u++) si[u] = g_colsrc[e + u];
        float hv[8];
        #pragma unroll
        for (int u = 0; u < 8; u++) hv[u] = g_h2s[si[u] * F2 + lane];
        #pragma unroll
        for (int u = 0; u < 8; u++) acc += hv[u];
    }
    for (; e < end; e++)
        acc += g_h2s[g_colsrc[e] * F2 + lane];

    float h = dn * acc + b2[lane];
    hout[n * F2 + lane] = h;

    float o = 0.f;
    #pragma unroll
    for (int k = 0; k < F2; k++) {
        float hk = __shfl_sync(0xFFFFFFFFu, h, k);
        o = fmaf(hk, sW[k * F2 + lane], o);
    }
    out[n * F2 + lane] = o + bc[lane];
}

// ---------------- launch -----------------------------------------------------
extern "C" void kernel_launch(void* const* d_in, const int* in_sizes, int n_in,
                              void* d_out, int out_size) {
    const float* x   = (const float*)d_in[0];
    const int*   ei  = (const int*)d_in[1];
    const float* W1  = (const float*)d_in[2];
    const float* b1  = (const float*)d_in[3];
    const float* W2  = (const float*)d_in[4];
    const float* b2  = (const float*)d_in[5];
    const float* Wc  = (const float*)d_in[6];
    const float* bc  = (const float*)d_in[7];

    const int* src = ei;
    const int* dst = ei + NE;

    float* out  = (float*)d_out;            // [NN, F2]
    float* hout = (float*)d_out + NN * F2;  // [NN, F2]

    static int smem_set = 0;
    if (!smem_set) {
        cudaFuncSetAttribute(k_gemm12, cudaFuncAttributeMaxDynamicSharedMemorySize,
                             G12_SMEM_FLOATS * 4);
        smem_set = 1;
    }

    int nb_nodes = (NN + 255) / 256;
    int nb_edges = (NE + 255) / 256;
    int nb_gemm  = (NN + 31) / 32;

    // CSR build
    k_count<<<nb_edges, 256>>>(dst);
    k_scan1<<<NBLK, SCAN_B>>>();
    k_scan3<<<nb_nodes, 256>>>();
    k_scatter<<<nb_edges, 256>>>(src, dst);

    // Layer 1: prescale -> aggregate (fp16 gathers) -> fused gemm1+gemm2
    k_prescale<<<(NN * 32 + 255) / 256, 256>>>(x);
    k_aggx<<<(NN * 32 + 255) / 256, 256>>>(x);
    k_gemm12<<<nb_gemm, 128, G12_SMEM_FLOATS * 4>>>(W1, b1, W2);

    // agg2 + classifier fused
    k_agg2g3<<<(NN * 32 + 255) / 256, 256>>>(b2, Wc, bc, out, hout);
}

// round 12
// speedup vs baseline: 1.7040x; 1.2851x over previous
#include <cuda_runtime.h>
#include <cuda_fp16.h>
#include <mma.h>
#include <math.h>

using namespace nvcuda;

#define NN      50000
#define NN_PAD  50016           // round up to 32 for tile-tail reads
#define NE      800000
#define F0      64
#define F1      128
#define F2      32
#define SCAN_B  1024
#define NBLK    ((NN + SCAN_B - 1) / SCAN_B)   // 49

// ---------------- scratch (static device globals) ----------------------------
__device__ __half2 g_xs[NN * 32];       // dinv[n]*x[n] fp16 payload (128B rows)
__device__ __half2 g_axh[NN_PAD * 32];  // aggregated x, fp16 row-major [n][64]
__device__ float   g_h2s[NN * F2];      // dinv[n] * (a1 @ W2)
__device__ float   g_dinv[NN];
__device__ __half  g_W1h[F0 * F1];
__device__ __half  g_W2h[F1 * F2];
__device__ int     g_cnt[NN];           // zero at load; self-zeroed by k_scan1
__device__ int     g_fill[NN];
__device__ int     g_rowptr[NN + 1];
__device__ int     g_blksum[64];
__device__ int     g_colsrc[NE];

// ---------------- CSR build (+ weight fp16 conversion piggybacked) -----------
__global__ void k_count(const int* __restrict__ dst,
                        const float* __restrict__ W1,
                        const float* __restrict__ W2) {
    int i = blockIdx.x * blockDim.x + threadIdx.x;
    if (i < F0 * F1) g_W1h[i] = __float2half(W1[i]);
    else if (i < F0 * F1 + F1 * F2) g_W2h[i - F0 * F1] = __float2half(W2[i - F0 * F1]);
    if (i < NE) atomicAdd(&g_cnt[dst[i]], 1);
}

__global__ void k_scan1() {
    __shared__ int s[SCAN_B];
    int tid = threadIdx.x;
    int i = blockIdx.x * SCAN_B + tid;
    int v = 0;
    if (i < NN) {
        v = g_cnt[i];
        g_cnt[i] = 0;                                 // reset for next replay
        g_dinv[i] = rsqrtf((float)(v + 1));           // +1 self loop
    }
    s[tid] = v;
    __syncthreads();
    #pragma unroll
    for (int off = 1; off < SCAN_B; off <<= 1) {
        int t = (tid >= off) ? s[tid - off] : 0;
        __syncthreads();
        s[tid] += t;
        __syncthreads();
    }
    if (i < NN) g_rowptr[i] = s[tid] - v;
    if (tid == SCAN_B - 1) g_blksum[blockIdx.x] = s[tid];
}

__global__ void __launch_bounds__(256) k_scan3() {
    __shared__ int s[64];
    int t = threadIdx.x;
    if (t < 64) s[t] = (t < NBLK) ? g_blksum[t] : 0;
    __syncthreads();
    #pragma unroll
    for (int off = 1; off < 64; off <<= 1) {
        int u = (t < 64 && t >= off) ? s[t - off] : 0;
        __syncthreads();
        if (t < 64) s[t] += u;
        __syncthreads();
    }
    int i = blockIdx.x * 256 + t;
    if (i < NN) {
        int blk = i >> 10;
        int add = blk ? s[blk - 1] : 0;
        int r = g_rowptr[i] + add;
        g_rowptr[i] = r;
        g_fill[i] = r;
    }
    if (i == 0) g_rowptr[NN] = NE;
}

__global__ void k_scatter(const int* __restrict__ src, const int* __restrict__ dst) {
    int e = blockIdx.x * blockDim.x + threadIdx.x;
    if (e < NE) {
        int pos = atomicAdd(&g_fill[dst[e]], 1);
        g_colsrc[pos] = src[e];
    }
}

// ---------------- Prescale: xs = half2(dinv[n] * x[n]) ----------------------
__global__ void __launch_bounds__(256) k_prescale(const float* __restrict__ x) {
    int idx = blockIdx.x * 256 + threadIdx.x;     // over NN*32 half2 slots
    if (idx >= NN * 32) return;
    int n = idx >> 5;
    float d = g_dinv[n];
    float2 v = ((const float2*)x)[idx];
    g_xs[idx] = __floats2half2_rn(d * v.x, d * v.y);
}

// ---------------- Aggregate x: fp16 gathers -> fp16 ax ----------------------
__global__ void __launch_bounds__(256) k_aggx(const float* __restrict__ x) {
    int gtid = blockIdx.x * blockDim.x + threadIdx.x;
    int n = gtid >> 5;
    int lane = gtid & 31;
    if (n >= NN) return;

    float dn = g_dinv[n];
    float2 sv = ((const float2*)x)[n * 32 + lane];
    float ax = dn * sv.x, ay = dn * sv.y;          // self term, fp32

    int e = g_rowptr[n], end = g_rowptr[n + 1];
    for (; e + 7 < end; e += 8) {
        int si[8];
        #pragma unroll
        for (int u = 0; u < 8; u++) si[u] = g_colsrc[e + u];
        __half2 hv[8];
        #pragma unroll
        for (int u = 0; u < 8; u++) hv[u] = g_xs[si[u] * 32 + lane];
        #pragma unroll
        for (int u = 0; u < 8; u++) {
            float2 f = __half22float2(hv[u]);
            ax += f.x; ay += f.y;
        }
    }
    for (; e < end; e++) {
        float2 f = __half22float2(g_xs[g_colsrc[e] * 32 + lane]);
        ax += f.x; ay += f.y;
    }
    g_axh[n * 32 + lane] = __floats2half2_rn(dn * ax, dn * ay);
}

// ---- Fused WMMA GEMM1+GEMM2: h2s = dinv * (relu(axh@W1 + b1) @ W2) ---------
// dyn smem bytes: sA 4096 | sW1 16384 | sW2 8192 | sC1 16384 | sB 8192 | sC2 4096
#define OFF_A   0
#define OFF_W1  4096
#define OFF_W2  20480
#define OFF_C1  28672
#define OFF_B   45056
#define OFF_C2  53248
#define G12_SMEM 57344
__global__ void __launch_bounds__(128) k_gemm12(const float* __restrict__ b1) {
    extern __shared__ unsigned char sm[];
    __half* sA  = (__half*)(sm + OFF_A);    // 32 x 64, row-major
    __half* sW1 = (__half*)(sm + OFF_W1);   // 64 x 128
    __half* sW2 = (__half*)(sm + OFF_W2);   // 128 x 32
    float*  sC1 = (float*)(sm + OFF_C1);    // 32 x 128
    __half* sB  = (__half*)(sm + OFF_B);    // 32 x 128
    float*  sC2 = (float*)(sm + OFF_C2);    // 32 x 32

    int tid = threadIdx.x;
    int wid = tid >> 5;
    int n0 = blockIdx.x * 32;

    // stage A (2048 halves = 256 uint4) and weights (8192+4096 halves)
    {
        const uint4* srcA = (const uint4*)(g_axh + n0 * 32);
        uint4* dA = (uint4*)sA;
        #pragma unroll
        for (int i = tid; i < 256; i += 128) dA[i] = srcA[i];
        const uint4* srcW1 = (const uint4*)g_W1h;
        uint4* dW1 = (uint4*)sW1;
        #pragma unroll
        for (int i = tid; i < 1024; i += 128) dW1[i] = srcW1[i];
        const uint4* srcW2 = (const uint4*)g_W2h;
        uint4* dW2 = (uint4*)sW2;
        #pragma unroll
        for (int i = tid; i < 512; i += 128) dW2[i] = srcW2[i];
    }
    __syncthreads();

    // phase 1: C1[32x128] = A[32x64] @ W1[64x128]; warp: 16 rows x 64 cols
    {
        int r0 = (wid & 1) * 16;
        int c0 = (wid >> 1) * 64;
        wmma::fragment<wmma::accumulator, 16, 16, 16, float> acc[4];
        #pragma unroll
        for (int j = 0; j < 4; j++) wmma::fill_fragment(acc[j], 0.f);

        #pragma unroll
        for (int k = 0; k < F0; k += 16) {
            wmma::fragment<wmma::matrix_a, 16, 16, 16, __half, wmma::row_major> af;
            wmma::load_matrix_sync(af, sA + r0 * F0 + k, F0);
            #pragma unroll
            for (int j = 0; j < 4; j++) {
                wmma::fragment<wmma::matrix_b, 16, 16, 16, __half, wmma::row_major> bf;
                wmma::load_matrix_sync(bf, sW1 + k * F1 + c0 + 16 * j, F1);
                wmma::mma_sync(acc[j], af, bf, acc[j]);
            }
        }
        #pragma unroll
        for (int j = 0; j < 4; j++)
            wmma::store_matrix_sync(sC1 + r0 * F1 + c0 + 16 * j, acc[j], F1,
                                    wmma::mem_row_major);
    }
    __syncthreads();

    // bias + relu + fp16 convert: sB = half(relu(sC1 + b1))
    for (int idx = tid; idx < 32 * 64; idx += 128) {   // 2048 col-pairs
        int n = idx >> 6, c2 = (idx & 63) * 2;
        float lo = fmaxf(sC1[n * F1 + c2]     + __ldg(&b1[c2]),     0.f);
        float hi = fmaxf(sC1[n * F1 + c2 + 1] + __ldg(&b1[c2 + 1]), 0.f);
        ((__half2*)sB)[n * 64 + (c2 >> 1)] = __floats2half2_rn(lo, hi);
    }
    __syncthreads();

    // phase 2: C2[32x32] = sB[32x128] @ W2[128x32]; warp: 16x16 tile
    {
        int r0 = (wid & 1) * 16;
        int c0 = (wid >> 1) * 16;
        wmma::fragment<wmma::accumulator, 16, 16, 16, float> acc;
        wmma::fill_fragment(acc, 0.f);
        #pragma unroll
        for (int k = 0; k < F1; k += 16) {
            wmma::fragment<wmma::matrix_a, 16, 16, 16, __half, wmma::row_major> af;
            wmma::fragment<wmma::matrix_b, 16, 16, 16, __half, wmma::row_major> bf;
            wmma::load_matrix_sync(af, sB + r0 * F1 + k, F1);
            wmma::load_matrix_sync(bf, sW2 + k * F2 + c0, F2);
            wmma::mma_sync(acc, af, bf, acc);
        }
        wmma::store_matrix_sync(sC2 + r0 * F2 + c0, acc, F2, wmma::mem_row_major);
    }
    __syncthreads();

    // h2s[n] = dinv[n] * C2[n], fp32 (float4 x2 per node)
    {
        int nl = tid >> 2;                   // 0..31
        int c  = (tid & 3) * 8;
        int n = n0 + nl;
        if (n < NN) {
            float dnn = g_dinv[n];
            float4 v0 = *(float4*)&sC2[nl * F2 + c];
            float4 v1 = *(float4*)&sC2[nl * F2 + c + 4];
            v0.x *= dnn; v0.y *= dnn; v0.z *= dnn; v0.w *= dnn;
            v1.x *= dnn; v1.y *= dnn; v1.z *= dnn; v1.w *= dnn;
            *(float4*)&g_h2s[n * F2 + c]     = v0;
            *(float4*)&g_h2s[n * F2 + c + 4] = v1;
        }
    }
}

// ------- Fused agg2 + classifier ---------------------------------------------
__global__ void __launch_bounds__(256) k_agg2g3(const float* __restrict__ b2,
                                                const float* __restrict__ Wc,
                                                const float* __restrict__ bc,
                                                float* __restrict__ out,
                                                float* __restrict__ hout) {
    __shared__ float sW[F2 * F2];
    int tid = threadIdx.x;
    for (int i = tid; i < F2 * F2; i += 256) sW[i] = Wc[i];
    __syncthreads();

    int gtid = blockIdx.x * 256 + tid;
    int n = gtid >> 5;
    int lane = gtid & 31;
    if (n >= NN) return;

    float dn = g_dinv[n];
    float acc = g_h2s[n * F2 + lane];              // self term (pre-scaled)

    int e = g_rowptr[n], end = g_rowptr[n + 1];
    for (; e + 7 < end; e += 8) {
        int si[8];
        #pragma unroll
        for (int u = 0; u < 8; u++) si[u] = g_colsrc[e + u];
        float hv[8];
        #pragma unroll
        for (int u = 0; u < 8; u++) hv[u] = g_h2s[si[u] * F2 + lane];
        #pragma unroll
        for (int u = 0; u < 8; u++) acc += hv[u];
    }
    for (; e < end; e++)
        acc += g_h2s[g_colsrc[e] * F2 + lane];

    float h = dn * acc + b2[lane];
    hout[n * F2 + lane] = h;

    float o = 0.f;
    #pragma unroll
    for (int k = 0; k < F2; k++) {
        float hk = __shfl_sync(0xFFFFFFFFu, h, k);
        o = fmaf(hk, sW[k * F2 + lane], o);
    }
    out[n * F2 + lane] = o + bc[lane];
}

// ---------------- launch -----------------------------------------------------
extern "C" void kernel_launch(void* const* d_in, const int* in_sizes, int n_in,
                              void* d_out, int out_size) {
    const float* x   = (const float*)d_in[0];
    const int*   ei  = (const int*)d_in[1];
    const float* W1  = (const float*)d_in[2];
    const float* b1  = (const float*)d_in[3];
    const float* W2  = (const float*)d_in[4];
    const float* b2  = (const float*)d_in[5];
    const float* Wc  = (const float*)d_in[6];
    const float* bc  = (const float*)d_in[7];

    const int* src = ei;
    const int* dst = ei + NE;

    float* out  = (float*)d_out;            // [NN, F2]
    float* hout = (float*)d_out + NN * F2;  // [NN, F2]

    static int smem_set = 0;
    if (!smem_set) {
        cudaFuncSetAttribute(k_gemm12, cudaFuncAttributeMaxDynamicSharedMemorySize,
                             G12_SMEM);
        smem_set = 1;
    }

    int nb_nodes = (NN + 255) / 256;
    int nb_edges = (NE + 255) / 256;
    int nb_gemm  = (NN + 31) / 32;

    // CSR build (+ fp16 weight conversion in k_count)
    k_count<<<nb_edges, 256>>>(dst, W1, W2);
    k_scan1<<<NBLK, SCAN_B>>>();
    k_scan3<<<nb_nodes, 256>>>();
    k_scatter<<<nb_edges, 256>>>(src, dst);

    // Layer 1: prescale -> aggregate (fp16) -> fused WMMA gemm1+gemm2
    k_prescale<<<(NN * 32 + 255) / 256, 256>>>(x);
    k_aggx<<<(NN * 32 + 255) / 256, 256>>>(x);
    k_gemm12<<<nb_gemm, 128, G12_SMEM>>>(b1);

    // agg2 + classifier fused
    k_agg2g3<<<(NN * 32 + 255) / 256, 256>>>(b2, Wc, bc, out, hout);
}